// round 1
// baseline (speedup 1.0000x reference)
#include <cuda_runtime.h>
#include <math.h>
#include <float.h>

#define B_   2
#define T_   2048
#define C_   2048
#define H_   16
#define KVH_ 4
#define HD_  128
#define M_   (B_*T_)          // 4096 rows

// ---------------- scratch (no allocations allowed) ----------------
__device__ float g_q[(size_t)M_ * 2048];
__device__ float g_k[(size_t)M_ * 512];
__device__ float g_v[(size_t)M_ * 512];
__device__ float g_y[(size_t)M_ * 2048];

// ---------------- fp32 SIMT GEMM: C[M,N] = A[M,K] @ B[K,N] ----------------
// BM=BN=128, BK=8, 256 threads, 8x8 micro-tile per thread.
#define GBM 128
#define GBN 128
#define GBK 8
#define AS_STRIDE 132   // padded, keeps float4 alignment, conflict-free stores

__global__ __launch_bounds__(256)
void gemm128(const float* __restrict__ A, const float* __restrict__ Bw,
             float* __restrict__ Cw, int N, int K) {
    __shared__ float As[GBK * AS_STRIDE];   // stored transposed: As[k][row]
    __shared__ float Bs[GBK * GBN];         // Bs[k][col]

    const int tid = threadIdx.x;
    const int tx = tid & 15;        // col group
    const int ty = tid >> 4;        // row group
    const int m0 = blockIdx.y * GBM;
    const int n0 = blockIdx.x * GBN;

    const int arow = tid >> 1;      // 0..127
    const int ac4  = tid & 1;       // which half of the 8-wide k strip
    const int brow = tid >> 5;      // 0..7
    const int bc4  = tid & 31;      // 0..31 -> col = bc4*4

    float acc[8][8];
#pragma unroll
    for (int i = 0; i < 8; i++)
#pragma unroll
        for (int j = 0; j < 8; j++) acc[i][j] = 0.0f;

    for (int k0 = 0; k0 < K; k0 += GBK) {
        float4 av = *(const float4*)(A  + (size_t)(m0 + arow) * K + k0 + ac4 * 4);
        float4 bv = *(const float4*)(Bw + (size_t)(k0 + brow) * N + n0 + bc4 * 4);
        __syncthreads();   // previous tile compute done before overwrite
        As[(ac4 * 4 + 0) * AS_STRIDE + arow] = av.x;
        As[(ac4 * 4 + 1) * AS_STRIDE + arow] = av.y;
        As[(ac4 * 4 + 2) * AS_STRIDE + arow] = av.z;
        As[(ac4 * 4 + 3) * AS_STRIDE + arow] = av.w;
        *(float4*)&Bs[brow * GBN + bc4 * 4] = bv;
        __syncthreads();

#pragma unroll
        for (int kk = 0; kk < GBK; kk++) {
            float4 a0 = *(const float4*)&As[kk * AS_STRIDE + ty * 8];
            float4 a1 = *(const float4*)&As[kk * AS_STRIDE + ty * 8 + 4];
            float4 b0 = *(const float4*)&Bs[kk * GBN + tx * 8];
            float4 b1 = *(const float4*)&Bs[kk * GBN + tx * 8 + 4];
            float a[8] = {a0.x, a0.y, a0.z, a0.w, a1.x, a1.y, a1.z, a1.w};
            float bb[8] = {b0.x, b0.y, b0.z, b0.w, b1.x, b1.y, b1.z, b1.w};
#pragma unroll
            for (int i = 0; i < 8; i++)
#pragma unroll
                for (int j = 0; j < 8; j++)
                    acc[i][j] = fmaf(a[i], bb[j], acc[i][j]);
        }
    }

#pragma unroll
    for (int i = 0; i < 8; i++) {
        float* cp = Cw + (size_t)(m0 + ty * 8 + i) * N + n0 + tx * 8;
        float4 c0 = make_float4(acc[i][0], acc[i][1], acc[i][2], acc[i][3]);
        float4 c1 = make_float4(acc[i][4], acc[i][5], acc[i][6], acc[i][7]);
        *(float4*)(cp)     = c0;
        *(float4*)(cp + 4) = c1;
    }
}

// ---------------- RoPE + RMSNorm (per head vector of 128) ----------------
// grid = B*T*(H+KVH) blocks, 32 threads each.
__global__ __launch_bounds__(32)
void rope_rms_kernel(float* __restrict__ q, float* __restrict__ k,
                     const float* __restrict__ cosp, const float* __restrict__ sinp) {
    const int n  = blockIdx.x;
    const int bt = n / (H_ + KVH_);
    const int hh = n - bt * (H_ + KVH_);
    float* p = (hh < H_) ? (q + (size_t)bt * 2048 + (size_t)hh * 128)
                         : (k + (size_t)bt * 512  + (size_t)(hh - H_) * 128);
    const int t = bt & (T_ - 1);
    const int l = threadIdx.x;

    float o1[2], o2[2];
    float ss = 0.0f;
#pragma unroll
    for (int u = 0; u < 2; u++) {
        int d = l + u * 32;
        float x1 = p[d];
        float x2 = p[d + 64];
        float c = cosp[t * 64 + d];
        float s = sinp[t * 64 + d];
        o1[u] = x1 * c + x2 * s;
        o2[u] = x2 * c - x1 * s;
        ss += o1[u] * o1[u] + o2[u] * o2[u];
    }
#pragma unroll
    for (int off = 16; off > 0; off >>= 1)
        ss += __shfl_xor_sync(0xffffffffu, ss, off);
    float r = rsqrtf(ss * (1.0f / 128.0f) + 1e-5f);
#pragma unroll
    for (int u = 0; u < 2; u++) {
        int d = l + u * 32;
        p[d]      = o1[u] * r;
        p[d + 64] = o2[u] * r;
    }
}

// ---------------- causal flash attention (GQA) ----------------
// 64 queries x 64 keys per tile, 256 threads (16x16), online softmax.
#define ABQ 64
#define ABK 64
#define QSTRIDE 65
#define VSTRIDE 132
#define PSTRIDE 68
#define ATT_SCALE 0.08838834764831845f   // 1/sqrt(128)

#define ATT_SMEM_FLOATS (128*QSTRIDE + 128*QSTRIDE + 64*VSTRIDE + 64*PSTRIDE)

__global__ __launch_bounds__(256)
void attn_kernel(const float* __restrict__ q, const float* __restrict__ k,
                 const float* __restrict__ v, float* __restrict__ y) {
    extern __shared__ float sm[];
    float* Qst = sm;                          // [128][65]  (d-major)
    float* Kst = Qst + 128 * QSTRIDE;         // [128][65]
    float* Vs  = Kst + 128 * QSTRIDE;         // [64][132]  (row-major)
    float* Ps  = Vs  + 64  * VSTRIDE;         // [64][68]

    const int tid = threadIdx.x;
    const int tx = tid & 15;    // 4 S-cols / 8 O-cols
    const int ty = tid >> 4;    // 4 rows
    const int qtile = blockIdx.x;
    const int bh = blockIdx.y;
    const int b  = bh >> 4;
    const int h  = bh & 15;
    const int kv = h >> 2;                 // n_rep = 4
    const int q0 = qtile * ABQ;

    // load Q tile (transposed into smem)
    {
        size_t qbase = ((size_t)(b * T_ + q0)) * 2048 + (size_t)h * 128;
#pragma unroll
        for (int it = 0; it < 8; it++) {
            int fidx = tid + it * 256;
            int row = fidx >> 5;
            int c4  = fidx & 31;
            float4 val = *(const float4*)(q + qbase + (size_t)row * 2048 + c4 * 4);
            Qst[(c4 * 4 + 0) * QSTRIDE + row] = val.x;
            Qst[(c4 * 4 + 1) * QSTRIDE + row] = val.y;
            Qst[(c4 * 4 + 2) * QSTRIDE + row] = val.z;
            Qst[(c4 * 4 + 3) * QSTRIDE + row] = val.w;
        }
    }

    float m_i[4], l_i[4], o[4][8];
#pragma unroll
    for (int i = 0; i < 4; i++) {
        m_i[i] = -FLT_MAX; l_i[i] = 0.0f;
#pragma unroll
        for (int c = 0; c < 8; c++) o[i][c] = 0.0f;
    }

    for (int jt = 0; jt <= qtile; jt++) {
        const int j0 = jt * ABK;
        __syncthreads();   // prior tile fully consumed (also orders Q stores on jt=0)
        {
            size_t kbase = ((size_t)(b * T_ + j0)) * 512 + (size_t)kv * 128;
#pragma unroll
            for (int it = 0; it < 8; it++) {
                int fidx = tid + it * 256;
                int row = fidx >> 5;
                int c4  = fidx & 31;
                float4 kvv = *(const float4*)(k + kbase + (size_t)row * 512 + c4 * 4);
                Kst[(c4 * 4 + 0) * QSTRIDE + row] = kvv.x;
                Kst[(c4 * 4 + 1) * QSTRIDE + row] = kvv.y;
                Kst[(c4 * 4 + 2) * QSTRIDE + row] = kvv.z;
                Kst[(c4 * 4 + 3) * QSTRIDE + row] = kvv.w;
                float4 vv = *(const float4*)(v + kbase + (size_t)row * 512 + c4 * 4);
                *(float4*)&Vs[row * VSTRIDE + c4 * 4] = vv;
            }
        }
        __syncthreads();

        // S = Q K^T  (4x4 per thread)
        float s_[4][4];
#pragma unroll
        for (int i = 0; i < 4; i++)
#pragma unroll
            for (int j = 0; j < 4; j++) s_[i][j] = 0.0f;

#pragma unroll 4
        for (int d = 0; d < 128; d++) {
            float qa[4], kb[4];
#pragma unroll
            for (int i = 0; i < 4; i++) qa[i] = Qst[d * QSTRIDE + ty * 4 + i];
#pragma unroll
            for (int j = 0; j < 4; j++) kb[j] = Kst[d * QSTRIDE + tx * 4 + j];
#pragma unroll
            for (int i = 0; i < 4; i++)
#pragma unroll
                for (int j = 0; j < 4; j++)
                    s_[i][j] = fmaf(qa[i], kb[j], s_[i][j]);
        }

        const bool diag = (jt == qtile);
#pragma unroll
        for (int i = 0; i < 4; i++) {
            const int qi = q0 + ty * 4 + i;
            float rm = -FLT_MAX;
#pragma unroll
            for (int j = 0; j < 4; j++) {
                float sv = s_[i][j] * ATT_SCALE;
                if (diag && (j0 + tx * 4 + j) > qi) sv = -FLT_MAX;
                s_[i][j] = sv;
                rm = fmaxf(rm, sv);
            }
#pragma unroll
            for (int off = 8; off > 0; off >>= 1)
                rm = fmaxf(rm, __shfl_xor_sync(0xffffffffu, rm, off));
            float mn = fmaxf(m_i[i], rm);
            float f  = __expf(m_i[i] - mn);
            float ps = 0.0f;
#pragma unroll
            for (int j = 0; j < 4; j++) {
                float p = __expf(s_[i][j] - mn);
                s_[i][j] = p;
                ps += p;
            }
#pragma unroll
            for (int off = 8; off > 0; off >>= 1)
                ps += __shfl_xor_sync(0xffffffffu, ps, off);
            l_i[i] = l_i[i] * f + ps;
            m_i[i] = mn;
#pragma unroll
            for (int c = 0; c < 8; c++) o[i][c] *= f;
#pragma unroll
            for (int j = 0; j < 4; j++)
                Ps[(ty * 4 + i) * PSTRIDE + tx * 4 + j] = s_[i][j];
        }
        __syncthreads();

        // O += P @ V
#pragma unroll 2
        for (int s = 0; s < ABK; s++) {
            float pv[4];
#pragma unroll
            for (int i = 0; i < 4; i++) pv[i] = Ps[(ty * 4 + i) * PSTRIDE + s];
            float4 v0 = *(const float4*)&Vs[s * VSTRIDE + tx * 8];
            float4 v1 = *(const float4*)&Vs[s * VSTRIDE + tx * 8 + 4];
#pragma unroll
            for (int i = 0; i < 4; i++) {
                o[i][0] = fmaf(pv[i], v0.x, o[i][0]);
                o[i][1] = fmaf(pv[i], v0.y, o[i][1]);
                o[i][2] = fmaf(pv[i], v0.z, o[i][2]);
                o[i][3] = fmaf(pv[i], v0.w, o[i][3]);
                o[i][4] = fmaf(pv[i], v1.x, o[i][4]);
                o[i][5] = fmaf(pv[i], v1.y, o[i][5]);
                o[i][6] = fmaf(pv[i], v1.z, o[i][6]);
                o[i][7] = fmaf(pv[i], v1.w, o[i][7]);
            }
        }
    }

#pragma unroll
    for (int i = 0; i < 4; i++) {
        float inv = 1.0f / l_i[i];
        float* yp = y + ((size_t)(b * T_ + q0 + ty * 4 + i)) * 2048 + (size_t)h * 128 + tx * 8;
        float4 r0 = make_float4(o[i][0] * inv, o[i][1] * inv, o[i][2] * inv, o[i][3] * inv);
        float4 r1 = make_float4(o[i][4] * inv, o[i][5] * inv, o[i][6] * inv, o[i][7] * inv);
        *(float4*)(yp)     = r0;
        *(float4*)(yp + 4) = r1;
    }
}

// ---------------- launch ----------------
extern "C" void kernel_launch(void* const* d_in, const int* in_sizes, int n_in,
                              void* d_out, int out_size) {
    const float* x    = (const float*)d_in[0];
    const float* cosp = (const float*)d_in[1];
    const float* sinp = (const float*)d_in[2];
    const float* wq   = (const float*)d_in[3];
    const float* wk   = (const float*)d_in[4];
    const float* wv   = (const float*)d_in[5];
    const float* wo   = (const float*)d_in[6];
    float* out = (float*)d_out;

    float *qp, *kp, *vp, *yp;
    cudaGetSymbolAddress((void**)&qp, g_q);
    cudaGetSymbolAddress((void**)&kp, g_k);
    cudaGetSymbolAddress((void**)&vp, g_v);
    cudaGetSymbolAddress((void**)&yp, g_y);

    const int smem_attn = ATT_SMEM_FLOATS * (int)sizeof(float);
    cudaFuncSetAttribute(attn_kernel, cudaFuncAttributeMaxDynamicSharedMemorySize, smem_attn);

    dim3 blk(256);
    // QKV projections
    gemm128<<<dim3(2048 / GBN, M_ / GBM), blk>>>(x, wq, qp, 2048, 2048);
    gemm128<<<dim3(512  / GBN, M_ / GBM), blk>>>(x, wk, kp, 512, 2048);
    gemm128<<<dim3(512  / GBN, M_ / GBM), blk>>>(x, wv, vp, 512, 2048);
    // RoPE + RMSNorm on q and k
    rope_rms_kernel<<<M_ * (H_ + KVH_), 32>>>(qp, kp, cosp, sinp);
    // causal attention
    attn_kernel<<<dim3(T_ / ABQ, B_ * H_), blk, smem_attn>>>(qp, kp, vp, yp);
    // output projection
    gemm128<<<dim3(2048 / GBN, M_ / GBM), blk>>>(yp, wo, out, 2048, 2048);
}

// round 3
// speedup vs baseline: 1.5128x; 1.5128x over previous
#include <cuda_runtime.h>
#include <cuda_bf16.h>
#include <math.h>
#include <float.h>
#include <stdint.h>

#define B_   2
#define T_   2048
#define C_   2048
#define H_   16
#define KVH_ 4
#define HD_  128
#define M_   (B_*T_)           // 4096
#define K3_  6144              // 3 * 2048 (split-K)
#define QKV_LD 3072

// ---------------- scratch ----------------
__device__ __nv_bfloat16 g_xs [(size_t)M_ * K3_];      // split x      [M][3K]
__device__ __nv_bfloat16 g_wb1[(size_t)3072 * K3_];    // split qkv W^T [3072][3K]
__device__ __nv_bfloat16 g_wb2[(size_t)2048 * K3_];    // split wo^T    [2048][3K]
__device__ __nv_bfloat16 g_ys [(size_t)M_ * K3_];      // split y      [M][3K]
__device__ float g_qkv[(size_t)M_ * QKV_LD];           // fused qkv fp32
__device__ float g_y  [(size_t)M_ * 2048];             // attention out fp32

// ---------------- split helpers ----------------
__device__ __forceinline__ void split2(float v, __nv_bfloat16& h, __nv_bfloat16& l) {
    h = __float2bfloat16_rn(v);
    l = __float2bfloat16_rn(v - __bfloat162float(h));
}

// A-side split: src fp32 [M][2048] -> dst bf16 [M][6144] = [hi | lo | hi]
__global__ __launch_bounds__(256)
void split_a_kernel(const float* __restrict__ src, __nv_bfloat16* __restrict__ dst) {
    int idx = blockIdx.x * 256 + threadIdx.x;        // covers M*2048/4
    int m = idx >> 9;
    int k = (idx & 511) << 2;
    float4 v = *(const float4*)(src + (size_t)m * 2048 + k);
    __nv_bfloat16 h0, h1, h2, h3, l0, l1, l2, l3;
    split2(v.x, h0, l0); split2(v.y, h1, l1);
    split2(v.z, h2, l2); split2(v.w, h3, l3);
    __nv_bfloat162 H0 = __halves2bfloat162(h0, h1), H1 = __halves2bfloat162(h2, h3);
    __nv_bfloat162 L0 = __halves2bfloat162(l0, l1), L1 = __halves2bfloat162(l2, l3);
    __nv_bfloat162* d0 = (__nv_bfloat162*)(dst + (size_t)m * K3_ + k);
    d0[0] = H0; d0[1] = H1;
    __nv_bfloat162* d1 = (__nv_bfloat162*)(dst + (size_t)m * K3_ + 2048 + k);
    d1[0] = L0; d1[1] = L1;
    __nv_bfloat162* d2 = (__nv_bfloat162*)(dst + (size_t)m * K3_ + 4096 + k);
    d2[0] = H0; d2[1] = H1;
}

// B-side transpose+split: src fp32 [2048][Ncols], dst bf16 rows pre-offset,
// dst[n][k]=hi, dst[n][2048+k]=hi, dst[n][4096+k]=lo  (row stride 6144)
__global__ __launch_bounds__(256)
void tsplit_b_kernel(const float* __restrict__ src, __nv_bfloat16* __restrict__ dst, int Ncols) {
    __shared__ float t[32][33];
    const int n0 = blockIdx.x * 32, k0 = blockIdx.y * 32;
    const int tx = threadIdx.x, ty = threadIdx.y;    // 32 x 8
#pragma unroll
    for (int i = 0; i < 4; i++)
        t[ty + i * 8][tx] = src[(size_t)(k0 + ty + i * 8) * Ncols + n0 + tx];
    __syncthreads();
#pragma unroll
    for (int i = 0; i < 4; i++) {
        float v = t[tx][ty + i * 8];
        __nv_bfloat16 h, l;
        split2(v, h, l);
        __nv_bfloat16* row = dst + (size_t)(n0 + ty + i * 8) * K3_ + k0 + tx;
        row[0]    = h;
        row[2048] = h;
        row[4096] = l;
    }
}

// ---------------- bf16 mma.sync GEMM ----------------
// C[M,N] = A'[M,K3] @ Bt'[N,K3]^T ; 128x128 tile, BK=32, 256 threads.
#define SMPAD 80   // bytes per 32-bf16 smem row

__device__ __forceinline__ uint32_t smem_u32(const void* p) {
    uint32_t a;
    asm("{ .reg .u64 t; cvta.to.shared.u64 t, %1; cvt.u32.u64 %0, t; }" : "=r"(a) : "l"(p));
    return a;
}
#define LDMX4(r0, r1, r2, r3, addr) \
    asm volatile("ldmatrix.sync.aligned.m8n8.x4.shared.b16 {%0,%1,%2,%3}, [%4];" \
        : "=r"(r0), "=r"(r1), "=r"(r2), "=r"(r3) : "r"(addr))
#define MMA16816(c, a0, a1, a2, a3, b0, b1) \
    asm volatile("mma.sync.aligned.m16n8k16.row.col.f32.bf16.bf16.f32 " \
        "{%0,%1,%2,%3}, {%4,%5,%6,%7}, {%8,%9}, {%0,%1,%2,%3};" \
        : "+f"((c)[0]), "+f"((c)[1]), "+f"((c)[2]), "+f"((c)[3]) \
        : "r"(a0), "r"(a1), "r"(a2), "r"(a3), "r"(b0), "r"(b1))

__global__ __launch_bounds__(256)
void gemm_bf16(const __nv_bfloat16* __restrict__ A, const __nv_bfloat16* __restrict__ Bt,
               float* __restrict__ C, int N) {
    __shared__ __align__(16) uint8_t sm[4 * 128 * SMPAD];   // A0,A1,B0,B1 (10240B each)
    const uint32_t smb = smem_u32(sm);

    const int tid = threadIdx.x;
    const int lane = tid & 31, wid = tid >> 5;
    const int wm = wid >> 1, wn = wid & 1;                 // 4x2 warps -> 32x64 per warp
    const int m0 = blockIdx.y * 128, n0 = blockIdx.x * 128;

    // global->smem staging indices: 2 chunks of 16B per thread per matrix
    const int row_g = tid >> 2;        // +64 for chunk 1 -> wait: 256 thr * 2 = 512 = 128 rows * 4
    const int c16   = tid & 3;

    float acc[2][8][4];
#pragma unroll
    for (int i = 0; i < 2; i++)
#pragma unroll
        for (int j = 0; j < 8; j++)
#pragma unroll
            for (int r = 0; r < 4; r++) acc[i][j][r] = 0.0f;

    const int nK = K3_ / 32;   // 192

    // prologue: load stage 0
    {
        const __nv_bfloat16* ap = A  + (size_t)(m0 + row_g) * K3_ + c16 * 8;
        const __nv_bfloat16* bp = Bt + (size_t)(n0 + row_g) * K3_ + c16 * 8;
        uint4 a0 = *(const uint4*)ap;
        uint4 a1 = *(const uint4*)(ap + (size_t)64 * K3_);
        uint4 b0 = *(const uint4*)bp;
        uint4 b1 = *(const uint4*)(bp + (size_t)64 * K3_);
        *(uint4*)(sm + row_g * SMPAD + c16 * 16)                     = a0;
        *(uint4*)(sm + (row_g + 64) * SMPAD + c16 * 16)              = a1;
        *(uint4*)(sm + 2 * 128 * SMPAD + row_g * SMPAD + c16 * 16)        = b0;
        *(uint4*)(sm + 2 * 128 * SMPAD + (row_g + 64) * SMPAD + c16 * 16) = b1;
    }
    __syncthreads();

    // ldmatrix lane address components
    const int lj = lane >> 3, lr = lane & 7;
    // A x4: row = wm*32 + it*16 + (lj&1)*8 + lr ; colbyte = kk*32 + (lj>>1)*16
    const uint32_t a_row_off = (uint32_t)((wm * 32 + ((lj & 1) << 3) + lr) * SMPAD + ((lj >> 1) << 4));
    // B x4 (2 n-tiles): row = wn*64 + pair*16 + (lj>>1)*8 + lr ; colbyte = kk*32 + (lj&1)*16
    const uint32_t b_row_off = (uint32_t)((wn * 64 + ((lj >> 1) << 3) + lr) * SMPAD + ((lj & 1) << 4));

    for (int it = 0; it < nK; it++) {
        const int buf = it & 1;
        uint4 na0, na1, nb0, nb1;
        if (it + 1 < nK) {
            const int k0 = (it + 1) << 5;
            const __nv_bfloat16* ap = A  + (size_t)(m0 + row_g) * K3_ + k0 + c16 * 8;
            const __nv_bfloat16* bp = Bt + (size_t)(n0 + row_g) * K3_ + k0 + c16 * 8;
            na0 = *(const uint4*)ap;
            na1 = *(const uint4*)(ap + (size_t)64 * K3_);
            nb0 = *(const uint4*)bp;
            nb1 = *(const uint4*)(bp + (size_t)64 * K3_);
        }

        const uint32_t sA = smb + buf * 128 * SMPAD;
        const uint32_t sB = smb + (2 + buf) * 128 * SMPAD;
#pragma unroll
        for (int kk = 0; kk < 2; kk++) {
            uint32_t af[2][4];
#pragma unroll
            for (int i = 0; i < 2; i++)
                LDMX4(af[i][0], af[i][1], af[i][2], af[i][3],
                      sA + a_row_off + i * 16 * SMPAD + kk * 32);
            uint32_t bf[8][2];
#pragma unroll
            for (int p = 0; p < 4; p++) {
                uint32_t r0, r1, r2, r3;
                LDMX4(r0, r1, r2, r3, sB + b_row_off + p * 16 * SMPAD + kk * 32);
                bf[2 * p][0] = r0; bf[2 * p][1] = r1;
                bf[2 * p + 1][0] = r2; bf[2 * p + 1][1] = r3;
            }
#pragma unroll
            for (int i = 0; i < 2; i++)
#pragma unroll
                for (int j = 0; j < 8; j++)
                    MMA16816(acc[i][j], af[i][0], af[i][1], af[i][2], af[i][3],
                             bf[j][0], bf[j][1]);
        }
        __syncthreads();
        if (it + 1 < nK) {
            const int nbuf = (it + 1) & 1;
            uint8_t* dA = sm + nbuf * 128 * SMPAD;
            uint8_t* dB = sm + (2 + nbuf) * 128 * SMPAD;
            *(uint4*)(dA + row_g * SMPAD + c16 * 16)        = na0;
            *(uint4*)(dA + (row_g + 64) * SMPAD + c16 * 16) = na1;
            *(uint4*)(dB + row_g * SMPAD + c16 * 16)        = nb0;
            *(uint4*)(dB + (row_g + 64) * SMPAD + c16 * 16) = nb1;
            __syncthreads();
        }
    }

    // epilogue
    const int cr = lane >> 2, cc = (lane & 3) << 1;
#pragma unroll
    for (int i = 0; i < 2; i++) {
        const int mrow = m0 + wm * 32 + i * 16 + cr;
#pragma unroll
        for (int j = 0; j < 8; j++) {
            const int col = n0 + wn * 64 + j * 8 + cc;
            *(float2*)(C + (size_t)mrow * N + col)       = make_float2(acc[i][j][0], acc[i][j][1]);
            *(float2*)(C + (size_t)(mrow + 8) * N + col) = make_float2(acc[i][j][2], acc[i][j][3]);
        }
    }
}

// ---------------- RoPE + RMSNorm ----------------
__global__ __launch_bounds__(32)
void rope_rms_kernel(float* __restrict__ qkv,
                     const float* __restrict__ cosp, const float* __restrict__ sinp) {
    const int n  = blockIdx.x;
    const int bt = n / (H_ + KVH_);
    const int hh = n - bt * (H_ + KVH_);
    float* p = qkv + (size_t)bt * QKV_LD +
               ((hh < H_) ? (size_t)hh * 128 : (size_t)(2048 + (hh - H_) * 128));
    const int t = bt & (T_ - 1);
    const int l = threadIdx.x;

    float o1[2], o2[2];
    float ss = 0.0f;
#pragma unroll
    for (int u = 0; u < 2; u++) {
        int d = l + u * 32;
        float x1 = p[d];
        float x2 = p[d + 64];
        float c = cosp[t * 64 + d];
        float s = sinp[t * 64 + d];
        o1[u] = x1 * c + x2 * s;
        o2[u] = x2 * c - x1 * s;
        ss += o1[u] * o1[u] + o2[u] * o2[u];
    }
#pragma unroll
    for (int off = 16; off > 0; off >>= 1)
        ss += __shfl_xor_sync(0xffffffffu, ss, off);
    float r = rsqrtf(ss * (1.0f / 128.0f) + 1e-5f);
#pragma unroll
    for (int u = 0; u < 2; u++) {
        int d = l + u * 32;
        p[d]      = o1[u] * r;
        p[d + 64] = o2[u] * r;
    }
}

// ---------------- causal flash attention (fp32 SIMT) ----------------
#define ABQ 64
#define ABK 64
#define QSTRIDE 65
#define VSTRIDE 132
#define PSTRIDE 68
#define ATT_SCALE 0.08838834764831845f
#define ATT_SMEM_FLOATS (128*QSTRIDE + 128*QSTRIDE + 64*VSTRIDE + 64*PSTRIDE)

__global__ __launch_bounds__(256)
void attn_kernel(const float* __restrict__ qkv, float* __restrict__ y) {
    extern __shared__ float smf[];
    float* Qst = smf;
    float* Kst = Qst + 128 * QSTRIDE;
    float* Vs  = Kst + 128 * QSTRIDE;
    float* Ps  = Vs  + 64  * VSTRIDE;

    const int tid = threadIdx.x;
    const int tx = tid & 15;
    const int ty = tid >> 4;
    const int qtile = blockIdx.x;
    const int bh = blockIdx.y;
    const int b  = bh >> 4;
    const int h  = bh & 15;
    const int kv = h >> 2;
    const int q0 = qtile * ABQ;

    {
        size_t qbase = ((size_t)(b * T_ + q0)) * QKV_LD + (size_t)h * 128;
#pragma unroll
        for (int it = 0; it < 8; it++) {
            int fidx = tid + it * 256;
            int row = fidx >> 5;
            int c4  = fidx & 31;
            float4 val = *(const float4*)(qkv + qbase + (size_t)row * QKV_LD + c4 * 4);
            Qst[(c4 * 4 + 0) * QSTRIDE + row] = val.x;
            Qst[(c4 * 4 + 1) * QSTRIDE + row] = val.y;
            Qst[(c4 * 4 + 2) * QSTRIDE + row] = val.z;
            Qst[(c4 * 4 + 3) * QSTRIDE + row] = val.w;
        }
    }

    float m_i[4], l_i[4], o[4][8];
#pragma unroll
    for (int i = 0; i < 4; i++) {
        m_i[i] = -FLT_MAX; l_i[i] = 0.0f;
#pragma unroll
        for (int c = 0; c < 8; c++) o[i][c] = 0.0f;
    }

    for (int jt = 0; jt <= qtile; jt++) {
        const int j0 = jt * ABK;
        __syncthreads();
        {
            size_t kbase = ((size_t)(b * T_ + j0)) * QKV_LD + 2048 + (size_t)kv * 128;
#pragma unroll
            for (int it = 0; it < 8; it++) {
                int fidx = tid + it * 256;
                int row = fidx >> 5;
                int c4  = fidx & 31;
                float4 kvv = *(const float4*)(qkv + kbase + (size_t)row * QKV_LD + c4 * 4);
                Kst[(c4 * 4 + 0) * QSTRIDE + row] = kvv.x;
                Kst[(c4 * 4 + 1) * QSTRIDE + row] = kvv.y;
                Kst[(c4 * 4 + 2) * QSTRIDE + row] = kvv.z;
                Kst[(c4 * 4 + 3) * QSTRIDE + row] = kvv.w;
                float4 vv = *(const float4*)(qkv + kbase + 512 + (size_t)row * QKV_LD + c4 * 4);
                *(float4*)&Vs[row * VSTRIDE + c4 * 4] = vv;
            }
        }
        __syncthreads();

        float s_[4][4];
#pragma unroll
        for (int i = 0; i < 4; i++)
#pragma unroll
            for (int j = 0; j < 4; j++) s_[i][j] = 0.0f;

#pragma unroll 4
        for (int d = 0; d < 128; d++) {
            float qa[4], kb[4];
#pragma unroll
            for (int i = 0; i < 4; i++) qa[i] = Qst[d * QSTRIDE + ty * 4 + i];
#pragma unroll
            for (int j = 0; j < 4; j++) kb[j] = Kst[d * QSTRIDE + tx * 4 + j];
#pragma unroll
            for (int i = 0; i < 4; i++)
#pragma unroll
                for (int j = 0; j < 4; j++)
                    s_[i][j] = fmaf(qa[i], kb[j], s_[i][j]);
        }

        const bool diag = (jt == qtile);
#pragma unroll
        for (int i = 0; i < 4; i++) {
            const int qi = q0 + ty * 4 + i;
            float rm = -FLT_MAX;
#pragma unroll
            for (int j = 0; j < 4; j++) {
                float sv = s_[i][j] * ATT_SCALE;
                if (diag && (j0 + tx * 4 + j) > qi) sv = -FLT_MAX;
                s_[i][j] = sv;
                rm = fmaxf(rm, sv);
            }
#pragma unroll
            for (int off = 8; off > 0; off >>= 1)
                rm = fmaxf(rm, __shfl_xor_sync(0xffffffffu, rm, off));
            float mn = fmaxf(m_i[i], rm);
            float f  = __expf(m_i[i] - mn);
            float ps = 0.0f;
#pragma unroll
            for (int j = 0; j < 4; j++) {
                float p = __expf(s_[i][j] - mn);
                s_[i][j] = p;
                ps += p;
            }
#pragma unroll
            for (int off = 8; off > 0; off >>= 1)
                ps += __shfl_xor_sync(0xffffffffu, ps, off);
            l_i[i] = l_i[i] * f + ps;
            m_i[i] = mn;
#pragma unroll
            for (int c = 0; c < 8; c++) o[i][c] *= f;
#pragma unroll
            for (int j = 0; j < 4; j++)
                Ps[(ty * 4 + i) * PSTRIDE + tx * 4 + j] = s_[i][j];
        }
        __syncthreads();

#pragma unroll 2
        for (int s = 0; s < ABK; s++) {
            float pv[4];
#pragma unroll
            for (int i = 0; i < 4; i++) pv[i] = Ps[(ty * 4 + i) * PSTRIDE + s];
            float4 v0 = *(const float4*)&Vs[s * VSTRIDE + tx * 8];
            float4 v1 = *(const float4*)&Vs[s * VSTRIDE + tx * 8 + 4];
#pragma unroll
            for (int i = 0; i < 4; i++) {
                o[i][0] = fmaf(pv[i], v0.x, o[i][0]);
                o[i][1] = fmaf(pv[i], v0.y, o[i][1]);
                o[i][2] = fmaf(pv[i], v0.z, o[i][2]);
                o[i][3] = fmaf(pv[i], v0.w, o[i][3]);
                o[i][4] = fmaf(pv[i], v1.x, o[i][4]);
                o[i][5] = fmaf(pv[i], v1.y, o[i][5]);
                o[i][6] = fmaf(pv[i], v1.z, o[i][6]);
                o[i][7] = fmaf(pv[i], v1.w, o[i][7]);
            }
        }
    }

#pragma unroll
    for (int i = 0; i < 4; i++) {
        float inv = 1.0f / l_i[i];
        float* yp = y + ((size_t)(b * T_ + q0 + ty * 4 + i)) * 2048 + (size_t)h * 128 + tx * 8;
        float4 r0 = make_float4(o[i][0] * inv, o[i][1] * inv, o[i][2] * inv, o[i][3] * inv);
        float4 r1 = make_float4(o[i][4] * inv, o[i][5] * inv, o[i][6] * inv, o[i][7] * inv);
        *(float4*)(yp)     = r0;
        *(float4*)(yp + 4) = r1;
    }
}

// ---------------- launch ----------------
extern "C" void kernel_launch(void* const* d_in, const int* in_sizes, int n_in,
                              void* d_out, int out_size) {
    const float* x    = (const float*)d_in[0];
    const float* cosp = (const float*)d_in[1];
    const float* sinp = (const float*)d_in[2];
    const float* wq   = (const float*)d_in[3];
    const float* wk   = (const float*)d_in[4];
    const float* wv   = (const float*)d_in[5];
    const float* wo   = (const float*)d_in[6];
    float* out = (float*)d_out;

    __nv_bfloat16 *xs, *wb1, *wb2, *ys;
    float *qkv, *y;
    cudaGetSymbolAddress((void**)&xs,  g_xs);
    cudaGetSymbolAddress((void**)&wb1, g_wb1);
    cudaGetSymbolAddress((void**)&wb2, g_wb2);
    cudaGetSymbolAddress((void**)&ys,  g_ys);
    cudaGetSymbolAddress((void**)&qkv, g_qkv);
    cudaGetSymbolAddress((void**)&y,   g_y);

    const int smem_attn = ATT_SMEM_FLOATS * (int)sizeof(float);
    cudaFuncSetAttribute(attn_kernel, cudaFuncAttributeMaxDynamicSharedMemorySize, smem_attn);

    dim3 tb(32, 8);
    // split x
    split_a_kernel<<<(M_ * 2048 / 4) / 256, 256>>>(x, xs);
    // transpose+split weights into Bt' rows
    tsplit_b_kernel<<<dim3(2048 / 32, 2048 / 32), tb>>>(wq, wb1, 2048);
    tsplit_b_kernel<<<dim3(512  / 32, 2048 / 32), tb>>>(wk, wb1 + (size_t)2048 * K3_, 512);
    tsplit_b_kernel<<<dim3(512  / 32, 2048 / 32), tb>>>(wv, wb1 + (size_t)2560 * K3_, 512);
    tsplit_b_kernel<<<dim3(2048 / 32, 2048 / 32), tb>>>(wo, wb2, 2048);

    // fused QKV projection (bf16 tensor cores, split-K compensated)
    gemm_bf16<<<dim3(3072 / 128, M_ / 128), 256>>>(xs, wb1, qkv, 3072);
    // RoPE + RMSNorm in place on q,k regions
    rope_rms_kernel<<<M_ * (H_ + KVH_), 32>>>(qkv, cosp, sinp);
    // causal attention
    attn_kernel<<<dim3(T_ / ABQ, B_ * H_), 256, smem_attn>>>(qkv, y);
    // split y, output projection
    split_a_kernel<<<(M_ * 2048 / 4) / 256, 256>>>(y, ys);
    gemm_bf16<<<dim3(2048 / 128, M_ / 128), 256>>>(ys, wb2, out, 2048);
}